// round 6
// baseline (speedup 1.0000x reference)
#include <cuda_runtime.h>
#include <cuda_fp16.h>
#include <math.h>
#include <stdint.h>

// ---------------------------------------------------------------------------
// Problem constants
// ---------------------------------------------------------------------------
#define NE_MAX 30000
#define NU_MAX 200000
#define NS_MAX 20000
#define EUE_MAX 1000000

// ---------------------------------------------------------------------------
// Device scratch
// ---------------------------------------------------------------------------
__device__ __align__(256) float g_WeT[768 * 128];   // W_email k-major [768][128]
__device__ __align__(256) float g_Wu[80 * 128];     // url KAN weight k-major [80][128] (padded)
__device__ __align__(256) float g_Wsn[16 * 128];    // sender KAN weight k-major [16][128]
__device__ __align__(256) float g_Wc[384 * 128];    // combined SAGE weight k-major [384][128]
__device__ float g_bc[128];
__device__ __align__(256) float g_Fu[(size_t)NU_MAX * 80];
__device__ __align__(256) float g_Fs[(size_t)NS_MAX * 16];
__device__ __align__(256) __half g_uh[(size_t)NU_MAX * 128];  // url embeddings fp16
__device__ __align__(256) float g_s[(size_t)NS_MAX * 128];
__device__ __align__(256) float g_X[(size_t)NE_MAX * 384]; // [agg_se | agg_ue | e]
__device__ __align__(256) float g_C[(size_t)NE_MAX * 256]; // [email_h | e]
__device__ int g_cnt_se[NE_MAX];
__device__ int g_cnt_ue[NE_MAX];
__device__ int g_off[NE_MAX + 1];
__device__ int g_wp[NE_MAX];
__device__ int g_part[256];
__device__ int g_sorted[EUE_MAX];
__device__ float g_sums[256];
__device__ float g_sumsq[256];
__device__ float g_scale[256];
__device__ float g_shift[256];

// ---------------------------------------------------------------------------
// Packed fp32x2 helpers
// ---------------------------------------------------------------------------
__device__ __forceinline__ float2 unpack2(unsigned long long v) {
    float2 f;
    asm("mov.b64 {%0, %1}, %2;" : "=f"(f.x), "=f"(f.y) : "l"(v));
    return f;
}
__device__ __forceinline__ unsigned long long fma2(unsigned long long a, unsigned long long b,
                                                   unsigned long long c) {
    unsigned long long d;
    asm("fma.rn.f32x2 %0, %1, %2, %3;" : "=l"(d) : "l"(a), "l"(b), "l"(c));
    return d;
}

// ---------------------------------------------------------------------------
// SIMT fp32x2 SGEMM v2: C[M,128] = act(A[M,K] @ Bk[K][128] + bias)
// A row-major (lda); Bk k-major [K][128]. K % 16 == 0.
// 128x128 tile/CTA, 256 threads, 8x8 per thread. BK=16, double-buffered.
// A tile stored pre-duplicated in SMEM ((v,v) pairs) -> no dup movs in the
// inner loop; B pairs read directly as u64. 32 FMA2 + 6 LDS.128 per k-step.
// SMEM (dynamic): A 2x16x264 floats, B 2x16x132 floats = 50688 B.
// ---------------------------------------------------------------------------
#define A_STRIDE 264  // 256 dup floats + 8 pad
#define B_STRIDE 132
#define A_BUF (16 * A_STRIDE)
#define B_BUF (16 * B_STRIDE)
#define GSMEM ((2 * A_BUF + 2 * B_BUF) * 4)

template <int ACT, bool DUAL, bool HOUT>  // ACT: 0=none 1=tanh 2=lrelu
__global__ void __launch_bounds__(256) sgemm2(
    const float* __restrict__ A, int lda,
    const float* __restrict__ Bk,
    const float* __restrict__ bias,
    void* __restrict__ Cp, int ldc,
    float* __restrict__ C2, int ldc2,
    int M, int K) {
    extern __shared__ float dyn[];
    float* As = dyn;              // [2][16][A_STRIDE]
    float* Bs = dyn + 2 * A_BUF;  // [2][16][B_STRIDE]

    int tid = threadIdx.x;
    int tx = tid & 15;
    int ty = tid >> 4;

    int bm = blockIdx.x * 128;
    int rowsA = M - bm;
    if (rowsA > 128) rowsA = 128;
    int nch = K >> 4;

    unsigned long long acc[8][4];
#pragma unroll
    for (int i = 0; i < 8; i++)
#pragma unroll
        for (int j = 0; j < 4; j++) acc[i][j] = 0ull;

    int a_row = tid >> 1;        // 0..127
    int a_kq = (tid & 1) * 8;    // 0 or 8
    int b_k = tid >> 4;          // 0..15
    int b_col = (tid & 15) * 8;  // 0..120

    // prologue: chunk 0 -> buffer 0
    {
        float4 av0 = make_float4(0.f, 0.f, 0.f, 0.f);
        float4 av1 = make_float4(0.f, 0.f, 0.f, 0.f);
        if (a_row < rowsA) {
            const float* p = A + (size_t)(bm + a_row) * lda + a_kq;
            av0 = *(const float4*)(p);
            av1 = *(const float4*)(p + 4);
        }
        float va[8] = {av0.x, av0.y, av0.z, av0.w, av1.x, av1.y, av1.z, av1.w};
#pragma unroll
        for (int j = 0; j < 8; j++)
            *(float2*)(As + (a_kq + j) * A_STRIDE + 2 * a_row) = make_float2(va[j], va[j]);
        const float* bp = Bk + (size_t)b_k * 128 + b_col;
        *(float4*)(Bs + b_k * B_STRIDE + b_col) = *(const float4*)(bp);
        *(float4*)(Bs + b_k * B_STRIDE + b_col + 4) = *(const float4*)(bp + 4);
    }
    __syncthreads();

    for (int c = 0; c < nch; c++) {
        int cur = c & 1;
        int nxt = cur ^ 1;
        bool have_next = (c + 1 < nch);
        float4 ga0 = make_float4(0.f, 0.f, 0.f, 0.f);
        float4 ga1 = make_float4(0.f, 0.f, 0.f, 0.f);
        float4 gb0 = make_float4(0.f, 0.f, 0.f, 0.f);
        float4 gb1 = make_float4(0.f, 0.f, 0.f, 0.f);
        if (have_next) {
            int k0 = (c + 1) * 16;
            if (a_row < rowsA) {
                const float* p = A + (size_t)(bm + a_row) * lda + k0 + a_kq;
                ga0 = *(const float4*)(p);
                ga1 = *(const float4*)(p + 4);
            }
            const float* bp = Bk + (size_t)(k0 + b_k) * 128 + b_col;
            gb0 = *(const float4*)(bp);
            gb1 = *(const float4*)(bp + 4);
        }

        const float* Ab = As + cur * A_BUF + ty * 16;
        const float* Bb = Bs + cur * B_BUF + tx * 8;
#pragma unroll
        for (int k = 0; k < 16; k++) {
            ulonglong2 a01 = *(const ulonglong2*)(Ab + k * A_STRIDE);
            ulonglong2 a23 = *(const ulonglong2*)(Ab + k * A_STRIDE + 4);
            ulonglong2 a45 = *(const ulonglong2*)(Ab + k * A_STRIDE + 8);
            ulonglong2 a67 = *(const ulonglong2*)(Ab + k * A_STRIDE + 12);
            ulonglong2 b03 = *(const ulonglong2*)(Bb + k * B_STRIDE);
            ulonglong2 b47 = *(const ulonglong2*)(Bb + k * B_STRIDE + 4);
            unsigned long long ad[8] = {a01.x, a01.y, a23.x, a23.y,
                                        a45.x, a45.y, a67.x, a67.y};
            unsigned long long bp[4] = {b03.x, b03.y, b47.x, b47.y};
#pragma unroll
            for (int i = 0; i < 8; i++) {
#pragma unroll
                for (int j = 0; j < 4; j++) acc[i][j] = fma2(ad[i], bp[j], acc[i][j]);
            }
        }

        if (have_next) {
            float* Asn = As + nxt * A_BUF;
            float va[8] = {ga0.x, ga0.y, ga0.z, ga0.w, ga1.x, ga1.y, ga1.z, ga1.w};
#pragma unroll
            for (int j = 0; j < 8; j++)
                *(float2*)(Asn + (a_kq + j) * A_STRIDE + 2 * a_row) = make_float2(va[j], va[j]);
            float* Bsn = Bs + nxt * B_BUF;
            *(float4*)(Bsn + b_k * B_STRIDE + b_col) = gb0;
            *(float4*)(Bsn + b_k * B_STRIDE + b_col + 4) = gb1;
        }
        __syncthreads();
    }

    // epilogue: thread (tx,ty) owns rows ty*8.., cols tx*8..
#pragma unroll
    for (int i = 0; i < 8; i++) {
        int r = bm + ty * 8 + i;
        if (r >= M) continue;
#pragma unroll
        for (int jp = 0; jp < 4; jp++) {
            int cc = tx * 8 + jp * 2;
            float2 v = unpack2(acc[i][jp]);
            if (bias) {
                v.x += __ldg(&bias[cc + 0]);
                v.y += __ldg(&bias[cc + 1]);
            }
            if (ACT == 1) {
                v.x = tanhf(v.x);
                v.y = tanhf(v.y);
            } else if (ACT == 2) {
                v.x = v.x >= 0.f ? v.x : 0.2f * v.x;
                v.y = v.y >= 0.f ? v.y : 0.2f * v.y;
            }
            if (HOUT) {
                *(__half2*)((__half*)Cp + (size_t)r * ldc + cc) = __floats2half2_rn(v.x, v.y);
            } else {
                *(float2*)((float*)Cp + (size_t)r * ldc + cc) = v;
            }
            if (DUAL) *(float2*)(C2 + (size_t)r * ldc2 + cc) = v;
        }
    }
}

// ---------------------------------------------------------------------------
// B-spline helpers
// ---------------------------------------------------------------------------
__device__ __forceinline__ float gknot(int i) {
    return (float)(i - 3) * 0.4f - 1.0f;
}

__device__ __forceinline__ void bspline8(float x, float* out) {
    float b[11];
#pragma unroll
    for (int i = 0; i < 11; i++) {
        b[i] = (x >= gknot(i) && x < gknot(i + 1)) ? 1.0f : 0.0f;
    }
#pragma unroll
    for (int j = 1; j <= 3; j++) {
#pragma unroll
        for (int i = 0; i <= 10 - j; i++) {
            float d1 = gknot(i + j) - gknot(i);
            float d2 = gknot(i + j + 1) - gknot(i + 1);
            b[i] = (x - gknot(i)) / d1 * b[i] + (gknot(i + j + 1) - x) / d2 * b[i + 1];
        }
    }
#pragma unroll
    for (int i = 0; i < 8; i++) out[i] = b[i];
}

__device__ __forceinline__ float silu(float x) {
    return x / (1.0f + expf(-x));
}

// ---------------------------------------------------------------------------
// Weight prep (k-major [K][128])
// ---------------------------------------------------------------------------
__global__ void prep_email_w(const float* __restrict__ W, float* __restrict__ Wt) {
    int idx = blockIdx.x * blockDim.x + threadIdx.x;
    if (idx < 768 * 128) {
        int k = idx / 128, o = idx % 128;
        Wt[idx] = W[o * 768 + k];
    }
}

__global__ void prep_url_w(const float* __restrict__ bw, const float* __restrict__ sw,
                           float* __restrict__ Wt) {
    int idx = blockIdx.x * blockDim.x + threadIdx.x;
    if (idx < 80 * 128) {
        int j = idx / 128, o = idx % 128;
        float v = 0.0f;
        if (j < 8) v = bw[o * 8 + j];
        else if (j < 72) v = sw[o * 64 + (j - 8)];
        Wt[idx] = v;
    }
}

__global__ void prep_snd_w(const float* __restrict__ bw, const float* __restrict__ sw,
                           float* __restrict__ Wt) {
    int idx = blockIdx.x * blockDim.x + threadIdx.x;
    if (idx < 16 * 128) {
        int j = idx / 128, o = idx % 128;
        float v = 0.0f;
        if (j < 1) v = bw[o];
        else if (j < 9) v = sw[o * 8 + (j - 1)];
        Wt[idx] = v;
    }
}

__global__ void prep_comb_w(const float* __restrict__ wlse, const float* __restrict__ wlue,
                            const float* __restrict__ wrse, const float* __restrict__ wrue,
                            const float* __restrict__ blse, const float* __restrict__ blue,
                            float* __restrict__ Wt, float* __restrict__ bc) {
    int idx = blockIdx.x * blockDim.x + threadIdx.x;
    if (idx < 384 * 128) {
        int k = idx / 128, o = idx % 128;
        float v;
        if (k < 128) v = wlse[o * 128 + k];
        else if (k < 256) v = wlue[o * 128 + (k - 128)];
        else v = wrse[o * 128 + (k - 256)] + wrue[o * 128 + (k - 256)];
        Wt[idx] = 0.5f * v;
    }
    if (idx < 128) bc[idx] = 0.5f * (blse[idx] + blue[idx]);
}

// ---------------------------------------------------------------------------
// KAN feature construction
// ---------------------------------------------------------------------------
__global__ void feat_url(const float* __restrict__ x, float* __restrict__ F, int n) {
    int gid = blockIdx.x * blockDim.x + threadIdx.x;
    if (gid < n * 8) {
        int nd = gid / 8, i = gid % 8;
        float v = x[gid];
        float* f = F + (size_t)nd * 80;
        f[i] = silu(v);
        float bs[8];
        bspline8(v, bs);
#pragma unroll
        for (int b = 0; b < 8; b++) f[8 + i * 8 + b] = bs[b];
        if (i == 0) {
#pragma unroll
            for (int j = 72; j < 80; j++) f[j] = 0.0f;
        }
    }
}

__global__ void feat_snd(const float* __restrict__ x, float* __restrict__ F, int n) {
    int gid = blockIdx.x * blockDim.x + threadIdx.x;
    if (gid < n) {
        float v = x[gid];
        float* f = F + (size_t)gid * 16;
        f[0] = silu(v);
        float bs[8];
        bspline8(v, bs);
#pragma unroll
        for (int b = 0; b < 8; b++) f[1 + b] = bs[b];
#pragma unroll
        for (int j = 9; j < 16; j++) f[j] = 0.0f;
    }
}

// ---------------------------------------------------------------------------
// SE aggregation: atomics (30k edges)
// ---------------------------------------------------------------------------
__global__ void zero_X_se(float* __restrict__ X, int n) {
    int idx = blockIdx.x * blockDim.x + threadIdx.x;
    int tot = n * 128;
    if (idx < tot) {
        int r = idx >> 7, c = idx & 127;
        X[(size_t)r * 384 + c] = 0.0f;
    }
}

__global__ void se_agg(const float* __restrict__ sfeat, const int* __restrict__ src,
                       const int* __restrict__ dst, int E, float* __restrict__ X,
                       int* __restrict__ cnt) {
    int w = (blockIdx.x * blockDim.x + threadIdx.x) >> 5;
    int lane = threadIdx.x & 31;
    int nw = (gridDim.x * blockDim.x) >> 5;
    for (int e = w; e < E; e += nw) {
        int sid = src[e];
        int did = dst[e];
#pragma unroll
        for (int q = 0; q < 4; q++) {
            int c = q * 32 + lane;
            float v = sfeat[(size_t)sid * 128 + c];
            atomicAdd(&X[(size_t)did * 384 + c], v);
        }
        if (lane == 0) atomicAdd(&cnt[did], 1);
    }
}

__global__ void norm_se(float* __restrict__ X, const int* __restrict__ cnt, int n) {
    int idx = blockIdx.x * blockDim.x + threadIdx.x;
    int tot = n * 128;
    if (idx < tot) {
        int r = idx >> 7, c = idx & 127;
        int k = cnt[r];
        X[(size_t)r * 384 + c] *= 1.0f / (float)(k > 0 ? k : 1);
    }
}

// ---------------------------------------------------------------------------
// UE aggregation: CSR bucketing + fp16 gather
// ---------------------------------------------------------------------------
__global__ void hist_kernel(const int* __restrict__ dst, int E, int* __restrict__ cnt) {
    int gid = blockIdx.x * blockDim.x + threadIdx.x;
    if (gid < E) atomicAdd(&cnt[dst[gid]], 1);
}

__global__ void scan1(const int* __restrict__ in, int* __restrict__ chunk,
                      int* __restrict__ part, int n) {
    __shared__ int sm[256];
    int t = threadIdx.x;
    int i = blockIdx.x * 256 + t;
    int v = (i < n) ? in[i] : 0;
    sm[t] = v;
    __syncthreads();
#pragma unroll
    for (int d = 1; d < 256; d <<= 1) {
        int x = (t >= d) ? sm[t - d] : 0;
        __syncthreads();
        sm[t] += x;
        __syncthreads();
    }
    if (i < n) chunk[i] = sm[t] - v;
    if (t == 255) part[blockIdx.x] = sm[255];
}

__global__ void scan2(int* __restrict__ part, int nb) {
    __shared__ int sm[128];
    int t = threadIdx.x;
    int v = (t < nb) ? part[t] : 0;
    sm[t] = v;
    __syncthreads();
#pragma unroll
    for (int d = 1; d < 128; d <<= 1) {
        int x = (t >= d) ? sm[t - d] : 0;
        __syncthreads();
        sm[t] += x;
        __syncthreads();
    }
    if (t < nb) part[t] = sm[t] - v;
}

__global__ void scan3(const int* __restrict__ chunk, const int* __restrict__ part,
                      int* __restrict__ off, int* __restrict__ wp, int n, int E) {
    int i = blockIdx.x * blockDim.x + threadIdx.x;
    if (i < n) {
        int o = chunk[i] + part[i >> 8];
        off[i] = o;
        wp[i] = o;
    }
    if (i == 0) off[n] = E;
}

__global__ void bucket_kernel(const int* __restrict__ src, const int* __restrict__ dst,
                              int E, int* __restrict__ wp, int* __restrict__ sorted) {
    int gid = blockIdx.x * blockDim.x + threadIdx.x;
    if (gid < E) {
        int p = atomicAdd(&wp[dst[gid]], 1);
        sorted[p] = src[gid];
    }
}

__global__ void ue_agg_h(const __half* __restrict__ u, const int* __restrict__ sorted,
                         const int* __restrict__ off, int ndst, float* __restrict__ X) {
    int w = (blockIdx.x * blockDim.x + threadIdx.x) >> 5;
    int lane = threadIdx.x & 31;
    int nw = (gridDim.x * blockDim.x) >> 5;
    for (int d = w; d < ndst; d += nw) {
        int a = off[d], b = off[d + 1];
        float4 ac0 = make_float4(0.f, 0.f, 0.f, 0.f);
        float4 ac1 = make_float4(0.f, 0.f, 0.f, 0.f);
        int e = a;
        for (; e + 2 <= b; e += 2) {
            uint2 r0 = *(const uint2*)(u + (size_t)sorted[e] * 128 + lane * 4);
            uint2 r1 = *(const uint2*)(u + (size_t)sorted[e + 1] * 128 + lane * 4);
            float2 f0 = __half22float2(*(__half2*)&r0.x);
            float2 f1 = __half22float2(*(__half2*)&r0.y);
            ac0.x += f0.x; ac0.y += f0.y; ac0.z += f1.x; ac0.w += f1.y;
            float2 g0 = __half22float2(*(__half2*)&r1.x);
            float2 g1 = __half22float2(*(__half2*)&r1.y);
            ac1.x += g0.x; ac1.y += g0.y; ac1.z += g1.x; ac1.w += g1.y;
        }
        if (e < b) {
            uint2 r0 = *(const uint2*)(u + (size_t)sorted[e] * 128 + lane * 4);
            float2 f0 = __half22float2(*(__half2*)&r0.x);
            float2 f1 = __half22float2(*(__half2*)&r0.y);
            ac0.x += f0.x; ac0.y += f0.y; ac0.z += f1.x; ac0.w += f1.y;
        }
        ac0.x += ac1.x; ac0.y += ac1.y; ac0.z += ac1.z; ac0.w += ac1.w;
        float inv = 1.0f / (float)((b - a) > 0 ? (b - a) : 1);
        float4 o4 = make_float4(ac0.x * inv, ac0.y * inv, ac0.z * inv, ac0.w * inv);
        *(float4*)(X + (size_t)d * 384 + 128 + lane * 4) = o4;
    }
}

// ---------------------------------------------------------------------------
// BatchNorm
// ---------------------------------------------------------------------------
__global__ void bn_stats(const float* __restrict__ C, int n,
                         float* __restrict__ sums, float* __restrict__ sumsq) {
    int c = threadIdx.x;
    float s = 0.f, q = 0.f;
    for (int r = blockIdx.x; r < n; r += gridDim.x) {
        float v = C[(size_t)r * 256 + c];
        s += v;
        q += v * v;
    }
    atomicAdd(&sums[c], s);
    atomicAdd(&sumsq[c], q);
}

__global__ void bn_finalize(const float* __restrict__ sums, const float* __restrict__ sumsq,
                            const float* __restrict__ gamma, const float* __restrict__ beta,
                            float* __restrict__ scale, float* __restrict__ shift, float invn) {
    int c = threadIdx.x;
    float m = sums[c] * invn;
    float var = sumsq[c] * invn - m * m;
    float sc = gamma[c] / sqrtf(var + 1e-5f);
    scale[c] = sc;
    shift[c] = beta[c] - m * sc;
}

// ---------------------------------------------------------------------------
// Classifier KAN
// ---------------------------------------------------------------------------
__global__ void classifier(const float* __restrict__ C, const float* __restrict__ scale,
                           const float* __restrict__ shift, const float* __restrict__ cb,
                           const float* __restrict__ cs, float* __restrict__ out, int n) {
    int w = (blockIdx.x * blockDim.x + threadIdx.x) >> 5;
    int lane = threadIdx.x & 31;
    int nw = (gridDim.x * blockDim.x) >> 5;
    for (int r = w; r < n; r += nw) {
        float a0 = 0.f, a1 = 0.f;
#pragma unroll
        for (int q = 0; q < 8; q++) {
            int i = q * 32 + lane;
            float x = C[(size_t)r * 256 + i];
            x = x * scale[i] + shift[i];
            float sl = silu(x);
            float bs[8];
            bspline8(x, bs);
            a0 += sl * __ldg(&cb[i]);
            a1 += sl * __ldg(&cb[256 + i]);
            const float* w0 = cs + i * 8;
            const float* w1 = cs + 2048 + i * 8;
#pragma unroll
            for (int b = 0; b < 8; b++) {
                a0 += bs[b] * __ldg(&w0[b]);
                a1 += bs[b] * __ldg(&w1[b]);
            }
        }
#pragma unroll
        for (int sft = 16; sft > 0; sft >>= 1) {
            a0 += __shfl_down_sync(0xFFFFFFFFu, a0, sft);
            a1 += __shfl_down_sync(0xFFFFFFFFu, a1, sft);
        }
        if (lane == 0) {
            out[(size_t)r * 2 + 0] = a0;
            out[(size_t)r * 2 + 1] = a1;
        }
    }
}

// ---------------------------------------------------------------------------
// Launch
// ---------------------------------------------------------------------------
static inline unsigned cdiv(unsigned a, unsigned b) { return (a + b - 1) / b; }

extern "C" void kernel_launch(void* const* d_in, const int* in_sizes, int n_in,
                              void* d_out, int out_size) {
    const float* email_x = (const float*)d_in[0];
    const float* url_x = (const float*)d_in[1];
    const float* sender_x = (const float*)d_in[2];
    const float* W_email = (const float*)d_in[3];
    const float* b_email = (const float*)d_in[4];
    const float* url_base_w = (const float*)d_in[5];
    const float* url_spline_w = (const float*)d_in[6];
    const float* snd_base_w = (const float*)d_in[7];
    const float* snd_spline_w = (const float*)d_in[8];
    const float* Wl_se = (const float*)d_in[9];
    const float* bl_se = (const float*)d_in[10];
    const float* Wr_se = (const float*)d_in[11];
    const float* Wl_ue = (const float*)d_in[15];
    const float* bl_ue = (const float*)d_in[16];
    const float* Wr_ue = (const float*)d_in[17];
    const float* bn_gamma = (const float*)d_in[18];
    const float* bn_beta = (const float*)d_in[19];
    const float* cls_base_w = (const float*)d_in[20];
    const float* cls_spline_w = (const float*)d_in[21];
    const int* ei_se_src = (const int*)d_in[22];
    const int* ei_se_dst = (const int*)d_in[23];
    const int* ei_ue_src = (const int*)d_in[26];
    const int* ei_ue_dst = (const int*)d_in[27];

    int N_E = in_sizes[0] / 768;
    int N_U = in_sizes[1] / 8;
    int N_S = in_sizes[2];
    int E_SE = in_sizes[22];
    int E_UE = in_sizes[26];

    float* out = (float*)d_out;

    float *WeT, *Wu, *Wsn, *Wc, *bc, *Fu, *Fs, *sbuf, *X, *C;
    __half* uh;
    float *sums, *sumsq, *scale, *shift;
    int *cnt_se, *cnt_ue, *off, *wp, *part, *sorted;
    cudaGetSymbolAddress((void**)&WeT, g_WeT);
    cudaGetSymbolAddress((void**)&Wu, g_Wu);
    cudaGetSymbolAddress((void**)&Wsn, g_Wsn);
    cudaGetSymbolAddress((void**)&Wc, g_Wc);
    cudaGetSymbolAddress((void**)&bc, g_bc);
    cudaGetSymbolAddress((void**)&Fu, g_Fu);
    cudaGetSymbolAddress((void**)&Fs, g_Fs);
    cudaGetSymbolAddress((void**)&uh, g_uh);
    cudaGetSymbolAddress((void**)&sbuf, g_s);
    cudaGetSymbolAddress((void**)&X, g_X);
    cudaGetSymbolAddress((void**)&C, g_C);
    cudaGetSymbolAddress((void**)&sums, g_sums);
    cudaGetSymbolAddress((void**)&sumsq, g_sumsq);
    cudaGetSymbolAddress((void**)&scale, g_scale);
    cudaGetSymbolAddress((void**)&shift, g_shift);
    cudaGetSymbolAddress((void**)&cnt_se, g_cnt_se);
    cudaGetSymbolAddress((void**)&cnt_ue, g_cnt_ue);
    cudaGetSymbolAddress((void**)&off, g_off);
    cudaGetSymbolAddress((void**)&wp, g_wp);
    cudaGetSymbolAddress((void**)&part, g_part);
    cudaGetSymbolAddress((void**)&sorted, g_sorted);

    cudaFuncSetAttribute(sgemm2<1, true, false>, cudaFuncAttributeMaxDynamicSharedMemorySize, GSMEM);
    cudaFuncSetAttribute(sgemm2<1, false, true>, cudaFuncAttributeMaxDynamicSharedMemorySize, GSMEM);
    cudaFuncSetAttribute(sgemm2<1, false, false>, cudaFuncAttributeMaxDynamicSharedMemorySize, GSMEM);
    cudaFuncSetAttribute(sgemm2<2, false, false>, cudaFuncAttributeMaxDynamicSharedMemorySize, GSMEM);

    // 0-3: memsets
    cudaMemsetAsync(cnt_se, 0, (size_t)N_E * sizeof(int), 0);
    cudaMemsetAsync(cnt_ue, 0, (size_t)N_E * sizeof(int), 0);
    cudaMemsetAsync(sums, 0, 256 * sizeof(float), 0);
    cudaMemsetAsync(sumsq, 0, 256 * sizeof(float), 0);
    // 4
    zero_X_se<<<cdiv(N_E * 128, 256), 256>>>(X, N_E);
    // 5
    prep_comb_w<<<cdiv(384 * 128, 256), 256>>>(Wl_se, Wl_ue, Wr_se, Wr_ue, bl_se, bl_ue, Wc, bc);
    // 6
    prep_email_w<<<cdiv(768 * 128, 256), 256>>>(W_email, WeT);
    // 7: email GEMM (profiled slot)
    sgemm2<1, true, false><<<cdiv(N_E, 128), 256, GSMEM>>>(
        email_x, 768, WeT, b_email, X + 256, 384, C + 128, 256, N_E, 768);
    // 8-10: url path
    prep_url_w<<<cdiv(80 * 128, 256), 256>>>(url_base_w, url_spline_w, Wu);
    feat_url<<<cdiv(N_U * 8, 256), 256>>>(url_x, Fu, N_U);
    sgemm2<1, false, true><<<cdiv(N_U, 128), 256, GSMEM>>>(
        Fu, 80, Wu, (const float*)nullptr, uh, 128, (float*)nullptr, 0, N_U, 80);
    // 11-13: sender path
    prep_snd_w<<<cdiv(16 * 128, 256), 256>>>(snd_base_w, snd_spline_w, Wsn);
    feat_snd<<<cdiv(N_S, 256), 256>>>(sender_x, Fs, N_S);
    sgemm2<1, false, false><<<cdiv(N_S, 128), 256, GSMEM>>>(
        Fs, 16, Wsn, (const float*)nullptr, sbuf, 128, (float*)nullptr, 0, N_S, 16);
    // 14-18: UE CSR
    hist_kernel<<<cdiv(E_UE, 256), 256>>>(ei_ue_dst, E_UE, cnt_ue);
    int nb = cdiv(N_E, 256);
    scan1<<<nb, 256>>>(cnt_ue, wp, part, N_E);
    scan2<<<1, 128>>>(part, nb);
    scan3<<<cdiv(N_E, 256), 256>>>(wp, part, off, wp, N_E, E_UE);
    bucket_kernel<<<cdiv(E_UE, 256), 256>>>(ei_ue_src, ei_ue_dst, E_UE, wp, sorted);
    // 19
    ue_agg_h<<<cdiv(N_E * 32, 256), 256>>>(uh, sorted, off, N_E, X);
    // 20-21: SE aggregate
    se_agg<<<cdiv(E_SE * 32, 256), 256>>>(sbuf, ei_se_src, ei_se_dst, E_SE, X, cnt_se);
    norm_se<<<cdiv(N_E * 128, 256), 256>>>(X, cnt_se, N_E);
    // 22: combine GEMM
    sgemm2<2, false, false><<<cdiv(N_E, 128), 256, GSMEM>>>(
        X, 384, Wc, bc, C, 256, (float*)nullptr, 0, N_E, 384);
    // 23-24: BN
    bn_stats<<<256, 256>>>(C, N_E, sums, sumsq);
    bn_finalize<<<1, 256>>>(sums, sumsq, bn_gamma, bn_beta, scale, shift, 1.0f / (float)N_E);
    // 25: classifier
    classifier<<<cdiv(N_E * 32, 256), 256>>>(C, scale, shift, cls_base_w, cls_spline_w, out, N_E);
}

// round 7
// speedup vs baseline: 1.1405x; 1.1405x over previous
#include <cuda_runtime.h>
#include <cuda_fp16.h>
#include <math.h>
#include <stdint.h>

// ---------------------------------------------------------------------------
// Problem constants
// ---------------------------------------------------------------------------
#define NE_MAX 30000
#define NU_MAX 200000
#define NS_MAX 20000
#define EUE_MAX 1000000

// ---------------------------------------------------------------------------
// Device scratch
// ---------------------------------------------------------------------------
__device__ __align__(256) float g_WeT[768 * 128];   // W_email k-major [768][128]
__device__ __align__(256) float g_Wu[80 * 128];     // url KAN weight k-major [80][128]
__device__ __align__(256) float g_Wsn[16 * 128];    // sender KAN weight k-major [16][128]
__device__ __align__(256) float g_Wc[384 * 128];    // combined SAGE weight k-major [384][128]
__device__ float g_bc[128];
__device__ __align__(256) float g_Fu[(size_t)NU_MAX * 80];
__device__ __align__(256) float g_Fs[(size_t)NS_MAX * 16];
__device__ __align__(256) __half g_uh[(size_t)NU_MAX * 128];  // url embeddings fp16
__device__ __align__(256) float g_s[(size_t)NS_MAX * 128];
__device__ __align__(256) float g_X[(size_t)NE_MAX * 384]; // [agg_se | agg_ue | e]
__device__ __align__(256) float g_C[(size_t)NE_MAX * 256]; // [email_h | e]
__device__ int g_cnt_se[NE_MAX];
__device__ int g_cnt_ue[NE_MAX];
__device__ int g_off[NE_MAX + 1];
__device__ int g_wp[NE_MAX];
__device__ int g_part[256];
__device__ int g_sorted[EUE_MAX];
__device__ float g_sums[256];
__device__ float g_sumsq[256];
__device__ float g_scale[256];
__device__ float g_shift[256];

// ---------------------------------------------------------------------------
// Packed fp32x2 helpers (sm_103a FFMA2 path)
// ---------------------------------------------------------------------------
__device__ __forceinline__ unsigned long long dup2(float x) {
    unsigned long long r;
    asm("mov.b64 %0, {%1, %1};" : "=l"(r) : "f"(x));
    return r;
}
__device__ __forceinline__ float2 unpack2(unsigned long long v) {
    float2 f;
    asm("mov.b64 {%0, %1}, %2;" : "=f"(f.x), "=f"(f.y) : "l"(v));
    return f;
}
__device__ __forceinline__ unsigned long long fma2(unsigned long long a, unsigned long long b,
                                                   unsigned long long c) {
    unsigned long long d;
    asm("fma.rn.f32x2 %0, %1, %2, %3;" : "=l"(d) : "l"(a), "l"(b), "l"(c));
    return d;
}

// ---------------------------------------------------------------------------
// SIMT fp32x2 SGEMM (round-5 structure): C[M,128] = act(A[M,K] @ Bk[K][128] + b)
// A row-major (lda); Bk k-major [K][128]. K % 8 == 0.
// 128x128 tile/CTA, 256 threads, 8x8/thread, BK=8, double-buffered SMEM.
// B fragments read directly as ulonglong2 (no pack movs).
// ---------------------------------------------------------------------------
template <int ACT, bool DUAL, bool HOUT>  // ACT: 0=none 1=tanh 2=lrelu
__global__ void __launch_bounds__(256) sgemm2(
    const float* __restrict__ A, int lda,
    const float* __restrict__ Bk,
    const float* __restrict__ bias,
    void* __restrict__ Cp, int ldc,
    float* __restrict__ C2, int ldc2,
    int M, int K) {
    __shared__ __align__(16) float As[2][8][132];
    __shared__ __align__(16) float Bs[2][8][132];

    int tid = threadIdx.x;
    int tx = tid % 16;
    int ty = tid / 16;

    int bm = blockIdx.x * 128;
    int rowsA = M - bm;
    if (rowsA > 128) rowsA = 128;
    int nch = K >> 3;

    unsigned long long acc[8][4];
#pragma unroll
    for (int i = 0; i < 8; i++)
#pragma unroll
        for (int j = 0; j < 4; j++) acc[i][j] = 0ull;

    int a_row = tid >> 1;        // 0..127
    int a_kq = (tid & 1) * 4;    // 0 or 4
    int b_k = tid >> 5;          // 0..7
    int b_col = (tid & 31) * 4;  // 0..124

    // prologue: chunk 0 -> buffer 0
    {
        float4 av = make_float4(0.f, 0.f, 0.f, 0.f);
        if (a_row < rowsA) av = *(const float4*)(A + (size_t)(bm + a_row) * lda + a_kq);
        As[0][a_kq + 0][a_row] = av.x;
        As[0][a_kq + 1][a_row] = av.y;
        As[0][a_kq + 2][a_row] = av.z;
        As[0][a_kq + 3][a_row] = av.w;
        float4 bv = *(const float4*)(Bk + (size_t)b_k * 128 + b_col);
        *(float4*)&Bs[0][b_k][b_col] = bv;
    }
    __syncthreads();

    for (int c = 0; c < nch; c++) {
        int cur = c & 1;
        int nxt = cur ^ 1;
        bool have_next = (c + 1 < nch);
        float4 ga = make_float4(0.f, 0.f, 0.f, 0.f);
        float4 gb = make_float4(0.f, 0.f, 0.f, 0.f);
        if (have_next) {
            int k0 = (c + 1) * 8;
            if (a_row < rowsA) ga = *(const float4*)(A + (size_t)(bm + a_row) * lda + k0 + a_kq);
            gb = *(const float4*)(Bk + (size_t)(k0 + b_k) * 128 + b_col);
        }

#pragma unroll
        for (int k = 0; k < 8; k++) {
            float4 a0 = *(const float4*)&As[cur][k][ty * 8];
            float4 a1 = *(const float4*)&As[cur][k][ty * 8 + 4];
            ulonglong2 b03 = *(const ulonglong2*)&Bs[cur][k][tx * 8];
            ulonglong2 b47 = *(const ulonglong2*)&Bs[cur][k][tx * 8 + 4];
            unsigned long long bp[4] = {b03.x, b03.y, b47.x, b47.y};
            float av8[8] = {a0.x, a0.y, a0.z, a0.w, a1.x, a1.y, a1.z, a1.w};
#pragma unroll
            for (int i = 0; i < 8; i++) {
                unsigned long long ad = dup2(av8[i]);
                acc[i][0] = fma2(ad, bp[0], acc[i][0]);
                acc[i][1] = fma2(ad, bp[1], acc[i][1]);
                acc[i][2] = fma2(ad, bp[2], acc[i][2]);
                acc[i][3] = fma2(ad, bp[3], acc[i][3]);
            }
        }

        if (have_next) {
            As[nxt][a_kq + 0][a_row] = ga.x;
            As[nxt][a_kq + 1][a_row] = ga.y;
            As[nxt][a_kq + 2][a_row] = ga.z;
            As[nxt][a_kq + 3][a_row] = ga.w;
            *(float4*)&Bs[nxt][b_k][b_col] = gb;
        }
        __syncthreads();
    }

    // epilogue
#pragma unroll
    for (int i = 0; i < 8; i++) {
        int r = bm + ty * 8 + i;
        if (r >= M) continue;
#pragma unroll
        for (int jp = 0; jp < 4; jp++) {
            int cc = tx * 8 + jp * 2;
            float2 v = unpack2(acc[i][jp]);
            if (bias) {
                v.x += __ldg(&bias[cc + 0]);
                v.y += __ldg(&bias[cc + 1]);
            }
            if (ACT == 1) {
                v.x = tanhf(v.x);
                v.y = tanhf(v.y);
            } else if (ACT == 2) {
                v.x = v.x >= 0.f ? v.x : 0.2f * v.x;
                v.y = v.y >= 0.f ? v.y : 0.2f * v.y;
            }
            if (HOUT) {
                *(__half2*)((__half*)Cp + (size_t)r * ldc + cc) = __floats2half2_rn(v.x, v.y);
            } else {
                *(float2*)((float*)Cp + (size_t)r * ldc + cc) = v;
            }
            if (DUAL) *(float2*)(C2 + (size_t)r * ldc2 + cc) = v;
        }
    }
}

// ---------------------------------------------------------------------------
// B-spline helpers
// ---------------------------------------------------------------------------
__device__ __forceinline__ float gknot(int i) {
    return (float)(i - 3) * 0.4f - 1.0f;
}

__device__ __forceinline__ void bspline8(float x, float* out) {
    float b[11];
#pragma unroll
    for (int i = 0; i < 11; i++) {
        b[i] = (x >= gknot(i) && x < gknot(i + 1)) ? 1.0f : 0.0f;
    }
#pragma unroll
    for (int j = 1; j <= 3; j++) {
#pragma unroll
        for (int i = 0; i <= 10 - j; i++) {
            float d1 = gknot(i + j) - gknot(i);
            float d2 = gknot(i + j + 1) - gknot(i + 1);
            b[i] = (x - gknot(i)) / d1 * b[i] + (gknot(i + j + 1) - x) / d2 * b[i + 1];
        }
    }
#pragma unroll
    for (int i = 0; i < 8; i++) out[i] = b[i];
}

__device__ __forceinline__ float silu(float x) {
    return x / (1.0f + expf(-x));
}

// ---------------------------------------------------------------------------
// Weight prep (k-major [K][128])
// ---------------------------------------------------------------------------
__global__ void prep_email_w(const float* __restrict__ W, float* __restrict__ Wt) {
    int idx = blockIdx.x * blockDim.x + threadIdx.x;
    if (idx < 768 * 128) {
        int k = idx / 128, o = idx % 128;
        Wt[idx] = W[o * 768 + k];
    }
}

__global__ void prep_url_w(const float* __restrict__ bw, const float* __restrict__ sw,
                           float* __restrict__ Wt) {
    int idx = blockIdx.x * blockDim.x + threadIdx.x;
    if (idx < 80 * 128) {
        int j = idx / 128, o = idx % 128;
        float v = 0.0f;
        if (j < 8) v = bw[o * 8 + j];
        else if (j < 72) v = sw[o * 64 + (j - 8)];
        Wt[idx] = v;
    }
}

__global__ void prep_snd_w(const float* __restrict__ bw, const float* __restrict__ sw,
                           float* __restrict__ Wt) {
    int idx = blockIdx.x * blockDim.x + threadIdx.x;
    if (idx < 16 * 128) {
        int j = idx / 128, o = idx % 128;
        float v = 0.0f;
        if (j < 1) v = bw[o];
        else if (j < 9) v = sw[o * 8 + (j - 1)];
        Wt[idx] = v;
    }
}

__global__ void prep_comb_w(const float* __restrict__ wlse, const float* __restrict__ wlue,
                            const float* __restrict__ wrse, const float* __restrict__ wrue,
                            const float* __restrict__ blse, const float* __restrict__ blue,
                            float* __restrict__ Wt, float* __restrict__ bc) {
    int idx = blockIdx.x * blockDim.x + threadIdx.x;
    if (idx < 384 * 128) {
        int k = idx / 128, o = idx % 128;
        float v;
        if (k < 128) v = wlse[o * 128 + k];
        else if (k < 256) v = wlue[o * 128 + (k - 128)];
        else v = wrse[o * 128 + (k - 256)] + wrue[o * 128 + (k - 256)];
        Wt[idx] = 0.5f * v;
    }
    if (idx < 128) bc[idx] = 0.5f * (blse[idx] + blue[idx]);
}

// ---------------------------------------------------------------------------
// KAN feature construction
// ---------------------------------------------------------------------------
__global__ void feat_url(const float* __restrict__ x, float* __restrict__ F, int n) {
    int gid = blockIdx.x * blockDim.x + threadIdx.x;
    if (gid < n * 8) {
        int nd = gid / 8, i = gid % 8;
        float v = x[gid];
        float* f = F + (size_t)nd * 80;
        f[i] = silu(v);
        float bs[8];
        bspline8(v, bs);
#pragma unroll
        for (int b = 0; b < 8; b++) f[8 + i * 8 + b] = bs[b];
        if (i == 0) {
#pragma unroll
            for (int j = 72; j < 80; j++) f[j] = 0.0f;
        }
    }
}

__global__ void feat_snd(const float* __restrict__ x, float* __restrict__ F, int n) {
    int gid = blockIdx.x * blockDim.x + threadIdx.x;
    if (gid < n) {
        float v = x[gid];
        float* f = F + (size_t)gid * 16;
        f[0] = silu(v);
        float bs[8];
        bspline8(v, bs);
#pragma unroll
        for (int b = 0; b < 8; b++) f[1 + b] = bs[b];
#pragma unroll
        for (int j = 9; j < 16; j++) f[j] = 0.0f;
    }
}

// ---------------------------------------------------------------------------
// SE aggregation: atomics (30k edges)
// ---------------------------------------------------------------------------
__global__ void zero_X_se(float* __restrict__ X, int n) {
    int idx = blockIdx.x * blockDim.x + threadIdx.x;
    int tot = n * 128;
    if (idx < tot) {
        int r = idx >> 7, c = idx & 127;
        X[(size_t)r * 384 + c] = 0.0f;
    }
}

__global__ void se_agg(const float* __restrict__ sfeat, const int* __restrict__ src,
                       const int* __restrict__ dst, int E, float* __restrict__ X,
                       int* __restrict__ cnt) {
    int w = (blockIdx.x * blockDim.x + threadIdx.x) >> 5;
    int lane = threadIdx.x & 31;
    int nw = (gridDim.x * blockDim.x) >> 5;
    for (int e = w; e < E; e += nw) {
        int sid = src[e];
        int did = dst[e];
#pragma unroll
        for (int q = 0; q < 4; q++) {
            int c = q * 32 + lane;
            float v = sfeat[(size_t)sid * 128 + c];
            atomicAdd(&X[(size_t)did * 384 + c], v);
        }
        if (lane == 0) atomicAdd(&cnt[did], 1);
    }
}

__global__ void norm_se(float* __restrict__ X, const int* __restrict__ cnt, int n) {
    int idx = blockIdx.x * blockDim.x + threadIdx.x;
    int tot = n * 128;
    if (idx < tot) {
        int r = idx >> 7, c = idx & 127;
        int k = cnt[r];
        X[(size_t)r * 384 + c] *= 1.0f / (float)(k > 0 ? k : 1);
    }
}

// ---------------------------------------------------------------------------
// UE aggregation: CSR bucketing + fp16 gather
// ---------------------------------------------------------------------------
__global__ void hist_kernel(const int* __restrict__ dst, int E, int* __restrict__ cnt) {
    int gid = blockIdx.x * blockDim.x + threadIdx.x;
    if (gid < E) atomicAdd(&cnt[dst[gid]], 1);
}

__global__ void scan1(const int* __restrict__ in, int* __restrict__ chunk,
                      int* __restrict__ part, int n) {
    __shared__ int sm[256];
    int t = threadIdx.x;
    int i = blockIdx.x * 256 + t;
    int v = (i < n) ? in[i] : 0;
    sm[t] = v;
    __syncthreads();
#pragma unroll
    for (int d = 1; d < 256; d <<= 1) {
        int x = (t >= d) ? sm[t - d] : 0;
        __syncthreads();
        sm[t] += x;
        __syncthreads();
    }
    if (i < n) chunk[i] = sm[t] - v;
    if (t == 255) part[blockIdx.x] = sm[255];
}

__global__ void scan2(int* __restrict__ part, int nb) {
    __shared__ int sm[128];
    int t = threadIdx.x;
    int v = (t < nb) ? part[t] : 0;
    sm[t] = v;
    __syncthreads();
#pragma unroll
    for (int d = 1; d < 128; d <<= 1) {
        int x = (t >= d) ? sm[t - d] : 0;
        __syncthreads();
        sm[t] += x;
        __syncthreads();
    }
    if (t < nb) part[t] = sm[t] - v;
}

__global__ void scan3(const int* __restrict__ chunk, const int* __restrict__ part,
                      int* __restrict__ off, int* __restrict__ wp, int n, int E) {
    int i = blockIdx.x * blockDim.x + threadIdx.x;
    if (i < n) {
        int o = chunk[i] + part[i >> 8];
        off[i] = o;
        wp[i] = o;
    }
    if (i == 0) off[n] = E;
}

__global__ void bucket_kernel(const int* __restrict__ src, const int* __restrict__ dst,
                              int E, int* __restrict__ wp, int* __restrict__ sorted) {
    int gid = blockIdx.x * blockDim.x + threadIdx.x;
    if (gid < E) {
        int p = atomicAdd(&wp[dst[gid]], 1);
        sorted[p] = src[gid];
    }
}

__global__ void ue_agg_h(const __half* __restrict__ u, const int* __restrict__ sorted,
                         const int* __restrict__ off, int ndst, float* __restrict__ X) {
    int w = (blockIdx.x * blockDim.x + threadIdx.x) >> 5;
    int lane = threadIdx.x & 31;
    int nw = (gridDim.x * blockDim.x) >> 5;
    for (int d = w; d < ndst; d += nw) {
        int a = off[d], b = off[d + 1];
        float4 ac0 = make_float4(0.f, 0.f, 0.f, 0.f);
        float4 ac1 = make_float4(0.f, 0.f, 0.f, 0.f);
        int e = a;
        for (; e + 2 <= b; e += 2) {
            uint2 r0 = *(const uint2*)(u + (size_t)sorted[e] * 128 + lane * 4);
            uint2 r1 = *(const uint2*)(u + (size_t)sorted[e + 1] * 128 + lane * 4);
            float2 f0 = __half22float2(*(__half2*)&r0.x);
            float2 f1 = __half22float2(*(__half2*)&r0.y);
            ac0.x += f0.x; ac0.y += f0.y; ac0.z += f1.x; ac0.w += f1.y;
            float2 g0 = __half22float2(*(__half2*)&r1.x);
            float2 g1 = __half22float2(*(__half2*)&r1.y);
            ac1.x += g0.x; ac1.y += g0.y; ac1.z += g1.x; ac1.w += g1.y;
        }
        if (e < b) {
            uint2 r0 = *(const uint2*)(u + (size_t)sorted[e] * 128 + lane * 4);
            float2 f0 = __half22float2(*(__half2*)&r0.x);
            float2 f1 = __half22float2(*(__half2*)&r0.y);
            ac0.x += f0.x; ac0.y += f0.y; ac0.z += f1.x; ac0.w += f1.y;
        }
        ac0.x += ac1.x; ac0.y += ac1.y; ac0.z += ac1.z; ac0.w += ac1.w;
        float inv = 1.0f / (float)((b - a) > 0 ? (b - a) : 1);
        float4 o4 = make_float4(ac0.x * inv, ac0.y * inv, ac0.z * inv, ac0.w * inv);
        *(float4*)(X + (size_t)d * 384 + 128 + lane * 4) = o4;
    }
}

// ---------------------------------------------------------------------------
// BatchNorm
// ---------------------------------------------------------------------------
__global__ void bn_stats(const float* __restrict__ C, int n,
                         float* __restrict__ sums, float* __restrict__ sumsq) {
    int c = threadIdx.x;
    float s = 0.f, q = 0.f;
    for (int r = blockIdx.x; r < n; r += gridDim.x) {
        float v = C[(size_t)r * 256 + c];
        s += v;
        q += v * v;
    }
    atomicAdd(&sums[c], s);
    atomicAdd(&sumsq[c], q);
}

__global__ void bn_finalize(const float* __restrict__ sums, const float* __restrict__ sumsq,
                            const float* __restrict__ gamma, const float* __restrict__ beta,
                            float* __restrict__ scale, float* __restrict__ shift, float invn) {
    int c = threadIdx.x;
    float m = sums[c] * invn;
    float var = sumsq[c] * invn - m * m;
    float sc = gamma[c] / sqrtf(var + 1e-5f);
    scale[c] = sc;
    shift[c] = beta[c] - m * sc;
}

// ---------------------------------------------------------------------------
// Classifier KAN
// ---------------------------------------------------------------------------
__global__ void classifier(const float* __restrict__ C, const float* __restrict__ scale,
                           const float* __restrict__ shift, const float* __restrict__ cb,
                           const float* __restrict__ cs, float* __restrict__ out, int n) {
    int w = (blockIdx.x * blockDim.x + threadIdx.x) >> 5;
    int lane = threadIdx.x & 31;
    int nw = (gridDim.x * blockDim.x) >> 5;
    for (int r = w; r < n; r += nw) {
        float a0 = 0.f, a1 = 0.f;
#pragma unroll
        for (int q = 0; q < 8; q++) {
            int i = q * 32 + lane;
            float x = C[(size_t)r * 256 + i];
            x = x * scale[i] + shift[i];
            float sl = silu(x);
            float bs[8];
            bspline8(x, bs);
            a0 += sl * __ldg(&cb[i]);
            a1 += sl * __ldg(&cb[256 + i]);
            const float* w0 = cs + i * 8;
            const float* w1 = cs + 2048 + i * 8;
#pragma unroll
            for (int b = 0; b < 8; b++) {
                a0 += bs[b] * __ldg(&w0[b]);
                a1 += bs[b] * __ldg(&w1[b]);
            }
        }
#pragma unroll
        for (int sft = 16; sft > 0; sft >>= 1) {
            a0 += __shfl_down_sync(0xFFFFFFFFu, a0, sft);
            a1 += __shfl_down_sync(0xFFFFFFFFu, a1, sft);
        }
        if (lane == 0) {
            out[(size_t)r * 2 + 0] = a0;
            out[(size_t)r * 2 + 1] = a1;
        }
    }
}

// ---------------------------------------------------------------------------
// Launch
// ---------------------------------------------------------------------------
static inline unsigned cdiv(unsigned a, unsigned b) { return (a + b - 1) / b; }

extern "C" void kernel_launch(void* const* d_in, const int* in_sizes, int n_in,
                              void* d_out, int out_size) {
    const float* email_x = (const float*)d_in[0];
    const float* url_x = (const float*)d_in[1];
    const float* sender_x = (const float*)d_in[2];
    const float* W_email = (const float*)d_in[3];
    const float* b_email = (const float*)d_in[4];
    const float* url_base_w = (const float*)d_in[5];
    const float* url_spline_w = (const float*)d_in[6];
    const float* snd_base_w = (const float*)d_in[7];
    const float* snd_spline_w = (const float*)d_in[8];
    const float* Wl_se = (const float*)d_in[9];
    const float* bl_se = (const float*)d_in[10];
    const float* Wr_se = (const float*)d_in[11];
    const float* Wl_ue = (const float*)d_in[15];
    const float* bl_ue = (const float*)d_in[16];
    const float* Wr_ue = (const float*)d_in[17];
    const float* bn_gamma = (const float*)d_in[18];
    const float* bn_beta = (const float*)d_in[19];
    const float* cls_base_w = (const float*)d_in[20];
    const float* cls_spline_w = (const float*)d_in[21];
    const int* ei_se_src = (const int*)d_in[22];
    const int* ei_se_dst = (const int*)d_in[23];
    const int* ei_ue_src = (const int*)d_in[26];
    const int* ei_ue_dst = (const int*)d_in[27];

    int N_E = in_sizes[0] / 768;
    int N_U = in_sizes[1] / 8;
    int N_S = in_sizes[2];
    int E_SE = in_sizes[22];
    int E_UE = in_sizes[26];

    float* out = (float*)d_out;

    float *WeT, *Wu, *Wsn, *Wc, *bc, *Fu, *Fs, *sbuf, *X, *C;
    __half* uh;
    float *sums, *sumsq, *scale, *shift;
    int *cnt_se, *cnt_ue, *off, *wp, *part, *sorted;
    cudaGetSymbolAddress((void**)&WeT, g_WeT);
    cudaGetSymbolAddress((void**)&Wu, g_Wu);
    cudaGetSymbolAddress((void**)&Wsn, g_Wsn);
    cudaGetSymbolAddress((void**)&Wc, g_Wc);
    cudaGetSymbolAddress((void**)&bc, g_bc);
    cudaGetSymbolAddress((void**)&Fu, g_Fu);
    cudaGetSymbolAddress((void**)&Fs, g_Fs);
    cudaGetSymbolAddress((void**)&uh, g_uh);
    cudaGetSymbolAddress((void**)&sbuf, g_s);
    cudaGetSymbolAddress((void**)&X, g_X);
    cudaGetSymbolAddress((void**)&C, g_C);
    cudaGetSymbolAddress((void**)&sums, g_sums);
    cudaGetSymbolAddress((void**)&sumsq, g_sumsq);
    cudaGetSymbolAddress((void**)&scale, g_scale);
    cudaGetSymbolAddress((void**)&shift, g_shift);
    cudaGetSymbolAddress((void**)&cnt_se, g_cnt_se);
    cudaGetSymbolAddress((void**)&cnt_ue, g_cnt_ue);
    cudaGetSymbolAddress((void**)&off, g_off);
    cudaGetSymbolAddress((void**)&wp, g_wp);
    cudaGetSymbolAddress((void**)&part, g_part);
    cudaGetSymbolAddress((void**)&sorted, g_sorted);

    // 0-3: memsets
    cudaMemsetAsync(cnt_se, 0, (size_t)N_E * sizeof(int), 0);
    cudaMemsetAsync(cnt_ue, 0, (size_t)N_E * sizeof(int), 0);
    cudaMemsetAsync(sums, 0, 256 * sizeof(float), 0);
    cudaMemsetAsync(sumsq, 0, 256 * sizeof(float), 0);
    // 4
    zero_X_se<<<cdiv(N_E * 128, 256), 256>>>(X, N_E);
    // 5
    prep_comb_w<<<cdiv(384 * 128, 256), 256>>>(Wl_se, Wl_ue, Wr_se, Wr_ue, bl_se, bl_ue, Wc, bc);
    // 6
    prep_email_w<<<cdiv(768 * 128, 256), 256>>>(W_email, WeT);
    // 7: email GEMM (profiled slot)
    sgemm2<1, true, false><<<cdiv(N_E, 128), 256>>>(
        email_x, 768, WeT, b_email, X + 256, 384, C + 128, 256, N_E, 768);
    // 8-10: url path
    prep_url_w<<<cdiv(80 * 128, 256), 256>>>(url_base_w, url_spline_w, Wu);
    feat_url<<<cdiv(N_U * 8, 256), 256>>>(url_x, Fu, N_U);
    sgemm2<1, false, true><<<cdiv(N_U, 128), 256>>>(
        Fu, 80, Wu, (const float*)nullptr, uh, 128, (float*)nullptr, 0, N_U, 80);
    // 11-13: sender path
    prep_snd_w<<<cdiv(16 * 128, 256), 256>>>(snd_base_w, snd_spline_w, Wsn);
    feat_snd<<<cdiv(N_S, 256), 256>>>(sender_x, Fs, N_S);
    sgemm2<1, false, false><<<cdiv(N_S, 128), 256>>>(
        Fs, 16, Wsn, (const float*)nullptr, sbuf, 128, (float*)nullptr, 0, N_S, 16);
    // 14-18: UE CSR
    hist_kernel<<<cdiv(E_UE, 256), 256>>>(ei_ue_dst, E_UE, cnt_ue);
    int nb = cdiv(N_E, 256);
    scan1<<<nb, 256>>>(cnt_ue, wp, part, N_E);
    scan2<<<1, 128>>>(part, nb);
    scan3<<<cdiv(N_E, 256), 256>>>(wp, part, off, wp, N_E, E_UE);
    bucket_kernel<<<cdiv(E_UE, 256), 256>>>(ei_ue_src, ei_ue_dst, E_UE, wp, sorted);
    // 19
    ue_agg_h<<<cdiv(N_E * 32, 256), 256>>>(uh, sorted, off, N_E, X);
    // 20-21: SE aggregate
    se_agg<<<cdiv(E_SE * 32, 256), 256>>>(sbuf, ei_se_src, ei_se_dst, E_SE, X, cnt_se);
    norm_se<<<cdiv(N_E * 128, 256), 256>>>(X, cnt_se, N_E);
    // 22: combine GEMM
    sgemm2<2, false, false><<<cdiv(N_E, 128), 256>>>(
        X, 384, Wc, bc, C, 256, (float*)nullptr, 0, N_E, 384);
    // 23-24: BN
    bn_stats<<<256, 256>>>(C, N_E, sums, sumsq);
    bn_finalize<<<1, 256>>>(sums, sumsq, bn_gamma, bn_beta, scale, shift, 1.0f / (float)N_E);
    // 25: classifier
    classifier<<<cdiv(N_E * 32, 256), 256>>>(C, scale, shift, cls_base_w, cls_spline_w, out, N_E);
}